// round 2
// baseline (speedup 1.0000x reference)
#include <cuda_runtime.h>
#include <cstdint>

// SpikeFP32Multiplier: A,B are [N, 32] float32 spike bits (MSB-first IEEE-754
// fp32 layout). Semantics: pack bits -> fp32, multiply (IEEE RNE), unpack bits.
// Pure HBM-streaming kernel: 768 MB total traffic at N = 2048*1024.

__global__ void spike_fp32_mul_kernel(const uint4* __restrict__ A,
                                      const uint4* __restrict__ B,
                                      float4* __restrict__ out,
                                      int n_elems) {
    int idx = blockIdx.x * blockDim.x + threadIdx.x;
    if (idx >= n_elems) return;

    const uint4* a = A + (size_t)idx * 8;   // 32 floats = 8 uint4
    const uint4* b = B + (size_t)idx * 8;

    // Pack: bit j (MSB-first) from word j. Input bits are exact 0.0f/1.0f,
    // so "nonzero word" == bit set; no FP compare needed.
    uint32_t ua = 0u, ub = 0u;
#pragma unroll
    for (int i = 0; i < 8; ++i) {
        uint4 wa = a[i];
        ua = (ua << 1) | (uint32_t)(wa.x != 0u);
        ua = (ua << 1) | (uint32_t)(wa.y != 0u);
        ua = (ua << 1) | (uint32_t)(wa.z != 0u);
        ua = (ua << 1) | (uint32_t)(wa.w != 0u);
    }
#pragma unroll
    for (int i = 0; i < 8; ++i) {
        uint4 wb = b[i];
        ub = (ub << 1) | (uint32_t)(wb.x != 0u);
        ub = (ub << 1) | (uint32_t)(wb.y != 0u);
        ub = (ub << 1) | (uint32_t)(wb.z != 0u);
        ub = (ub << 1) | (uint32_t)(wb.w != 0u);
    }

    // IEEE-754 fp32 multiply, round-to-nearest-even (default nvcc: no FTZ).
    float prod = __uint_as_float(ua) * __uint_as_float(ub);
    uint32_t up = __float_as_uint(prod);

    // Unpack MSB-first into 32 floats (0.0f / 1.0f).
    float4* o = out + (size_t)idx * 8;
#pragma unroll
    for (int i = 0; i < 8; ++i) {
        float4 w;
        w.x = (float)((up >> (31 - (i * 4 + 0))) & 1u);
        w.y = (float)((up >> (31 - (i * 4 + 1))) & 1u);
        w.z = (float)((up >> (31 - (i * 4 + 2))) & 1u);
        w.w = (float)((up >> (31 - (i * 4 + 3))) & 1u);
        o[i] = w;
    }
}

extern "C" void kernel_launch(void* const* d_in, const int* in_sizes, int n_in,
                              void* d_out, int out_size) {
    const uint4* A = (const uint4*)d_in[0];
    const uint4* B = (const uint4*)d_in[1];
    float4* out = (float4*)d_out;

    int n_elems = in_sizes[0] / 32;  // each element owns 32 spike-bit floats

    const int block = 256;
    int grid = (n_elems + block - 1) / block;
    spike_fp32_mul_kernel<<<grid, block>>>(A, B, out, n_elems);
}

// round 3
// speedup vs baseline: 1.7084x; 1.7084x over previous
#include <cuda_runtime.h>
#include <cstdint>

// SpikeFP32Multiplier, warp-cooperative version.
// A,B: [N, 32] float32 spike bits, MSB-first IEEE-754 layout.
// Lane l of a warp owns bit position l (memory index), i.e. IEEE bit (31-l).
// ballot packs the 32 predicates in one instruction; brev fixes MSB-first.
// All global accesses are perfectly coalesced (1 line / 1 wavefront per instr).

static constexpr int ELEMS_PER_WARP = 8;

__global__ void spike_fp32_mul_ballot(const uint32_t* __restrict__ A,
                                      const uint32_t* __restrict__ B,
                                      uint32_t* __restrict__ out,
                                      int n_elems) {
    const int lane = threadIdx.x & 31;
    const int warp = (blockIdx.x * blockDim.x + threadIdx.x) >> 5;
    const int e0 = warp * ELEMS_PER_WARP;
    if (e0 >= n_elems) return;

    // Batch all loads first for MLP (16 outstanding LDG.32 per lane).
    uint32_t a[ELEMS_PER_WARP], b[ELEMS_PER_WARP];
#pragma unroll
    for (int i = 0; i < ELEMS_PER_WARP; ++i) {
        size_t off = (size_t)(e0 + i) * 32 + lane;
        a[i] = A[off];
        b[i] = B[off];
    }

#pragma unroll
    for (int i = 0; i < ELEMS_PER_WARP; ++i) {
        // ballot bit l = (lane l word nonzero); brev -> IEEE bit (31-l).
        uint32_t ua = __brev(__ballot_sync(0xFFFFFFFFu, a[i] != 0u));
        uint32_t ub = __brev(__ballot_sync(0xFFFFFFFFu, b[i] != 0u));

        // IEEE-754 fp32 multiply, RNE, subnormal-aware (no -ftz).
        float p = __uint_as_float(ua) * __uint_as_float(ub);
        uint32_t up = __float_as_uint(p);

        // Lane l emits IEEE bit (31-l) as float 1.0f/0.0f bit pattern.
        uint32_t bitset = (up << lane) & 0x80000000u;
        out[(size_t)(e0 + i) * 32 + lane] = bitset ? 0x3F800000u : 0u;
    }
}

extern "C" void kernel_launch(void* const* d_in, const int* in_sizes, int n_in,
                              void* d_out, int out_size) {
    const uint32_t* A = (const uint32_t*)d_in[0];
    const uint32_t* B = (const uint32_t*)d_in[1];
    uint32_t* out = (uint32_t*)d_out;

    int n_elems = in_sizes[0] / 32;

    const int block = 256;                       // 8 warps per block
    int warps_needed = (n_elems + ELEMS_PER_WARP - 1) / ELEMS_PER_WARP;
    int grid = (warps_needed * 32 + block - 1) / block;
    spike_fp32_mul_ballot<<<grid, block>>>(A, B, out, n_elems);
}

// round 4
// speedup vs baseline: 1.7317x; 1.0136x over previous
#include <cuda_runtime.h>
#include <cstdint>

// SpikeFP32Multiplier, warp-cooperative ballot version, v3.
// A,B: [N, 32] float32 spike bits, MSB-first IEEE-754 layout.
// Lane l owns memory word (31-l) of each element, so:
//   ballot bit l == (word 31-l nonzero) == IEEE bit l  -> no __brev needed.
// All global accesses are one 128B line per warp instruction (fully coalesced).
// __ldcs/__stcs: evict-first streaming (768 MB through 126 MB L2, zero reuse).

static constexpr int ELEMS_PER_WARP = 8;

__global__ void spike_fp32_mul_ballot3(const uint32_t* __restrict__ A,
                                       const uint32_t* __restrict__ B,
                                       uint32_t* __restrict__ out,
                                       int n_elems) {
    const int lane = threadIdx.x & 31;
    const int warp = (blockIdx.x * blockDim.x + threadIdx.x) >> 5;
    const int e0 = warp * ELEMS_PER_WARP;
    if (e0 >= n_elems) return;

    const int w = 31 - lane;  // memory word index owned by this lane

    // Batch all loads first: 16 outstanding LDG.32 per lane (MLP=16).
    uint32_t a[ELEMS_PER_WARP], b[ELEMS_PER_WARP];
#pragma unroll
    for (int i = 0; i < ELEMS_PER_WARP; ++i) {
        size_t off = (size_t)(e0 + i) * 32 + w;
        a[i] = __ldcs(A + off);
        b[i] = __ldcs(B + off);
    }

#pragma unroll
    for (int i = 0; i < ELEMS_PER_WARP; ++i) {
        // ballot bit l = (word 31-l != 0) = IEEE bit l. Direct pack.
        uint32_t ua = __ballot_sync(0xFFFFFFFFu, a[i] != 0u);
        uint32_t ub = __ballot_sync(0xFFFFFFFFu, b[i] != 0u);

        // IEEE-754 fp32 multiply, RNE, subnormal-aware (no -ftz).
        float p = __uint_as_float(ua) * __uint_as_float(ub);
        uint32_t up = __float_as_uint(p);

        // Lane l emits IEEE bit l as float 1.0f/0.0f bit pattern at word 31-l.
        uint32_t val = (up >> lane) & 1u ? 0x3F800000u : 0u;
        __stcs(out + (size_t)(e0 + i) * 32 + w, val);
    }
}

extern "C" void kernel_launch(void* const* d_in, const int* in_sizes, int n_in,
                              void* d_out, int out_size) {
    const uint32_t* A = (const uint32_t*)d_in[0];
    const uint32_t* B = (const uint32_t*)d_in[1];
    uint32_t* out = (uint32_t*)d_out;

    int n_elems = in_sizes[0] / 32;

    const int block = 256;  // 8 warps per block
    int warps_needed = (n_elems + ELEMS_PER_WARP - 1) / ELEMS_PER_WARP;
    int grid = (warps_needed * 32 + block - 1) / block;
    spike_fp32_mul_ballot3<<<grid, block>>>(A, B, out, n_elems);
}